// round 11
// baseline (speedup 1.0000x reference)
#include <cuda_runtime.h>
#include <cuda_bf16.h>

#define BB 32
#define TT 36
#define NN 10000
#define FF 3
#define RR 20
#define HH 10
#define SL 3                                // time slices
#define TSL (TT/SL)                         // 12 timesteps per slice
#define CHUNKS 10                           // node chunks; 1000 nodes each
#define NODES_PER_CHUNK (NN / CHUNKS)       // 1000
#define ACTIVE_THREADS (NODES_PER_CHUNK/4)  // 250 threads own 4 nodes
#define GROUPS (BB*CHUNKS)                  // 320 (b,chunk) groups
#define PRED_ELEMS (BB*HH*NN)               // 3,200,000
#define REG_ELEMS  (BB*HH*RR)               // 6,400
#define NAN_CAP    (BB*NN)
#define ROW (NN*FF)                         // 30000 floats per (b,t) row

// Scratch (device globals — no allocation allowed)
__device__ float g_s[BB][SL][NN];           // per-slice NaN-masked sums
__device__ float g_c[BB][SL][NN];           // per-slice valid counts
__device__ float g_ps[BB][CHUNKS][RR];      // region partial sums
__device__ float g_pc[BB][CHUNKS][RR];      // region partial counts
__device__ int   g_cnt[GROUPS];             // per-(b,chunk) slice counters
__device__ unsigned g_done = 0;             // completed mid-phase groups
__device__ int   g_nan_count = 0;
__device__ int   g_nan_list[NAN_CAP];

// ---------------------------------------------------------------------------
// ONE kernel. grid = (CHUNKS, BB, SL), block = 256 (250 active for node work).
// Level 1: every block streams its (b, chunk, slice): 4 nodes/thread, 12 t.
// Level 2: last slice-block per (b,chunk) combines slices -> time_mean,
//          writes pred output, computes region partials (overlaps streaming).
// Level 3: last mid-block finalizes (g1/g2, regional output, NaN patch).
__global__ void __launch_bounds__(256) k_all(const float* __restrict__ seq,
                                             const void* __restrict__ cid_raw,
                                             float* __restrict__ out) {
    const int tid   = threadIdx.x;
    const int lane  = tid & 31;
    const int warp  = tid >> 5;
    const int chunk = blockIdx.x;
    const int b     = blockIdx.y;
    const int sl    = blockIdx.z;
    const bool active = (tid < ACTIVE_THREADS);
    const int n0 = chunk * NODES_PER_CHUNK + tid * 4;

    __shared__ int   s_elect;
    __shared__ int   s_fin;
    __shared__ int   s_is64;
    __shared__ float s_rs[8][RR];
    __shared__ float s_rc[8][RR];

    // ---------------- Level 1: streaming ----------------
    if (active) {
        float s0=0.f,s1=0.f,s2=0.f,s3=0.f;
        float c0=0.f,c1=0.f,c2=0.f,c3=0.f;
        const float* base = seq + ((size_t)(b * TT + sl * TSL) * NN + n0) * FF;
        #pragma unroll 12
        for (int t = 0; t < TSL; t++) {
            const float* p = base + (size_t)t * ROW;
            float4 v0 = __ldg((const float4*)(p));
            float4 v1 = __ldg((const float4*)(p + 4));
            float4 v2 = __ldg((const float4*)(p + 8));
            float a0 = v0.x, a1 = v0.w, a2 = v1.z, a3 = v2.y;
            if (a0 == a0) { s0 += a0; c0 += 1.f; }
            if (a1 == a1) { s1 += a1; c1 += 1.f; }
            if (a2 == a2) { s2 += a2; c2 += 1.f; }
            if (a3 == a3) { s3 += a3; c3 += 1.f; }
        }
        float4 sv; sv.x=s0; sv.y=s1; sv.z=s2; sv.w=s3;
        float4 cv; cv.x=c0; cv.y=c1; cv.z=c2; cv.w=c3;
        *(float4*)&g_s[b][sl][n0] = sv;
        *(float4*)&g_c[b][sl][n0] = cv;
    }

    // elect last slice-block of this (b,chunk)
    __threadfence();
    __syncthreads();
    if (tid == 0) {
        int old = atomicAdd(&g_cnt[b * CHUNKS + chunk], 1);
        s_elect = (old == SL - 1);
    }
    __syncthreads();
    if (!s_elect) return;
    __threadfence();   // acquire: all 3 slices' partials visible

    // ---------------- Level 2: mid (combine + pred + region) ----------------
    // dtype detect (int64 vs int32 cluster_id): warp 0, parallel ballot
    if (warp == 0) {
        const int* c32 = (const int*)cid_raw;
        int ok = 1;
        #pragma unroll
        for (int k = 0; k < 4; k++) {
            int idx = (lane * 4 + k) * 2;
            int lo = c32[idx], hi = c32[idx + 1];
            if (hi != 0 || (unsigned)lo >= 64u) ok = 0;
        }
        unsigned bal = __ballot_sync(0xffffffffu, ok);
        if (lane == 0) s_is64 = (bal == 0xffffffffu);
    }

    float s0=0.f,s1=0.f,s2=0.f,s3=0.f;
    float c0=0.f,c1=0.f,c2=0.f,c3=0.f;
    if (active) {
        #pragma unroll
        for (int s = 0; s < SL; s++) {
            float4 sv = *(const float4*)&g_s[b][s][n0];
            float4 cv = *(const float4*)&g_c[b][s][n0];
            s0 += sv.x; s1 += sv.y; s2 += sv.z; s3 += sv.w;
            c0 += cv.x; c1 += cv.y; c2 += cv.z; c3 += cv.w;
        }
    }
    float m0 = s0/c0, m1 = s1/c1, m2 = s2/c2, m3 = s3/c3;  // 0/0 -> NaN

    if (active) {
        float4 r; r.x = m0; r.y = m1; r.z = m2; r.w = m3;
        float* ob = out + (size_t)b * (HH * NN) + n0;
        #pragma unroll
        for (int h = 0; h < HH; h++)
            *(float4*)(ob + h * NN) = r;

        // record all-NaN nodes (expected never: 0.05^36)
        if (c0 == 0.f) { int i = atomicAdd(&g_nan_count, 1); if (i < NAN_CAP) g_nan_list[i] = b * NN + n0;     }
        if (c1 == 0.f) { int i = atomicAdd(&g_nan_count, 1); if (i < NAN_CAP) g_nan_list[i] = b * NN + n0 + 1; }
        if (c2 == 0.f) { int i = atomicAdd(&g_nan_count, 1); if (i < NAN_CAP) g_nan_list[i] = b * NN + n0 + 2; }
        if (c3 == 0.f) { int i = atomicAdd(&g_nan_count, 1); if (i < NAN_CAP) g_nan_list[i] = b * NN + n0 + 3; }
    }

    __syncthreads();   // s_is64 ready

    int r0=-1, r1=-1, r2=-1, r3=-1;
    if (active) {
        if (s_is64) {
            const long long* c64 = (const long long*)cid_raw;
            r0=(int)c64[n0]; r1=(int)c64[n0+1]; r2=(int)c64[n0+2]; r3=(int)c64[n0+3];
        } else {
            const int* c32 = (const int*)cid_raw;
            int4 cv = __ldg((const int4*)(c32 + n0));
            r0=cv.x; r1=cv.y; r2=cv.z; r3=cv.w;
        }
    }
    float v0 = (c0>0.f)?m0:0.f, v1 = (c1>0.f)?m1:0.f;
    float v2 = (c2>0.f)?m2:0.f, v3 = (c3>0.f)?m3:0.f;
    float k0 = (c0>0.f)?1.f:0.f, k1 = (c1>0.f)?1.f:0.f;
    float k2 = (c2>0.f)?1.f:0.f, k3 = (c3>0.f)?1.f:0.f;

    // per-warp region reduction (deterministic shuffles)
    #pragma unroll
    for (int r = 0; r < RR; r++) {
        float s = 0.f, c = 0.f;
        if (r0 == r) { s += v0; c += k0; }
        if (r1 == r) { s += v1; c += k1; }
        if (r2 == r) { s += v2; c += k2; }
        if (r3 == r) { s += v3; c += k3; }
        #pragma unroll
        for (int o = 16; o > 0; o >>= 1) {
            s += __shfl_xor_sync(0xffffffffu, s, o);
            c += __shfl_xor_sync(0xffffffffu, c, o);
        }
        if (lane == 0) { s_rs[warp][r] = s; s_rc[warp][r] = c; }
    }
    __syncthreads();

    if (tid < RR) {
        float s = 0.f, c = 0.f;
        #pragma unroll
        for (int w = 0; w < 8; w++) { s += s_rs[w][tid]; c += s_rc[w][tid]; }
        g_ps[b][chunk][tid] = s;
        g_pc[b][chunk][tid] = c;
    }

    // elect the last mid-block of all 320
    __threadfence();
    __syncthreads();
    if (tid == 0) {
        unsigned v = atomicAdd(&g_done, 1u);
        s_fin = (v == GROUPS - 1u);
    }
    __syncthreads();
    if (!s_fin) return;
    __threadfence();   // acquire: all groups' partials + NaN list visible

    // ---------------- Level 3: finalize ----------------
    __shared__ float s_rsum[BB*RR];
    __shared__ float s_rcnt[BB*RR];
    __shared__ float sh0[256], sh1[256], sh2[256], sh3[256];
    const int t = tid;

    for (int i = t; i < BB*RR; i += 256) {
        int bb = i / RR, rr = i % RR;
        float s = 0.f, c = 0.f;
        #pragma unroll
        for (int ch = 0; ch < CHUNKS; ch++) { s += g_ps[bb][ch][rr]; c += g_pc[bb][ch][rr]; }
        s_rsum[i] = s; s_rcnt[i] = c;
    }
    __syncthreads();

    // g1 = total_sum/total_cnt (regions partition nodes; H-tiling cancels);
    // g2 = mean of valid region-means
    float ts=0.f, tc=0.f, ms=0.f, mc=0.f;
    for (int i = t; i < BB*RR; i += 256) {
        float s = s_rsum[i], c = s_rcnt[i];
        ts += s; tc += c;
        if (c > 0.f) { ms += s / c; mc += 1.f; }
    }
    sh0[t]=ts; sh1[t]=tc; sh2[t]=ms; sh3[t]=mc;
    __syncthreads();
    #pragma unroll
    for (int o = 128; o > 0; o >>= 1) {
        if (t < o) { sh0[t]+=sh0[t+o]; sh1[t]+=sh1[t+o]; sh2[t]+=sh2[t+o]; sh3[t]+=sh3[t+o]; }
        __syncthreads();
    }
    const float g1 = sh0[0] / sh1[0];
    const float g2 = sh2[0] / sh3[0];

    // regional output [B, H, R] (independent of h)
    for (int i = t; i < REG_ELEMS; i += 256) {
        int bb = i / (HH * RR);
        int rr = i % RR;
        float c = s_rcnt[bb * RR + rr];
        out[PRED_ELEMS + i] = (c > 0.f) ? (s_rsum[bb * RR + rr] / c) : g2;
    }

    // NaN fixup in pred output (expected 0 entries; order-independent writes)
    int cnt = g_nan_count;
    if (cnt > NAN_CAP) cnt = NAN_CAP;
    for (int i = t; i < cnt; i += 256) {
        int code = g_nan_list[i];
        int bb = code / NN, n = code % NN;
        float* ob = out + (size_t)bb * (HH * NN) + n;
        #pragma unroll
        for (int h = 0; h < HH; h++) ob[h * NN] = g1;
    }
    __syncthreads();

    // reset counters for graph replay
    for (int i = t; i < GROUPS; i += 256) g_cnt[i] = 0;
    if (t == 0) { g_done = 0; g_nan_count = 0; }
}

// ---------------------------------------------------------------------------
extern "C" void kernel_launch(void* const* d_in, const int* in_sizes, int n_in,
                              void* d_out, int out_size) {
    const float* seq = (const float*)d_in[0];
    const void*  cid = d_in[1];
    float* out = (float*)d_out;

    dim3 gs(CHUNKS, BB, SL);
    k_all<<<gs, 256>>>(seq, cid, out);
}

// round 12
// speedup vs baseline: 1.2406x; 1.2406x over previous
#include <cuda_runtime.h>
#include <cuda_bf16.h>

#define BB 32
#define TT 36
#define NN 10000
#define FF 3
#define RR 20
#define HH 10
#define CHUNKS 20                           // node chunks; 512 nodes each (last partial)
#define NODES_PER_CHUNK 512
#define PRED_ELEMS (BB*HH*NN)               // 3,200,000
#define REG_ELEMS  (BB*HH*RR)               // 6,400
#define NAN_CAP    (BB*NN)
#define ROW (NN*FF)                         // 30000 floats per (b,t) row

// Scratch (device globals — no allocation allowed)
__device__ float g_ps[BB][CHUNKS][RR];      // region partial sums
__device__ float g_pc[BB][CHUNKS][RR];      // region partial counts
__device__ int   g_nan_count = 0;
__device__ int   g_nan_list[NAN_CAP];

// ---------------------------------------------------------------------------
// Kernel A: stream + time-mean + pred write + region partials, one pass.
// grid = (CHUNKS, BB) = 640 blocks, block = 256 threads, 2 nodes per thread.
// Channel 0 of nodes (n0, n0+1) sits at floats 0 and 3 of the 6-float pair:
// two aligned LDG.64 cover both; the skipped 8 bytes are fetched anyway by
// neighboring threads' sectors, so DRAM traffic is unchanged.
__global__ void __launch_bounds__(256) k_main(const float* __restrict__ seq,
                                              const void* __restrict__ cid_raw,
                                              float* __restrict__ out) {
    const int tid   = threadIdx.x;
    const int lane  = tid & 31;
    const int warp  = tid >> 5;
    const int chunk = blockIdx.x;
    const int b     = blockIdx.y;
    const int n0    = chunk * NODES_PER_CHUNK + tid * 2;
    const bool active = (n0 < NN);          // n0 even, NN even -> n0+1 also valid

    __shared__ int   s_is64;
    __shared__ float s_rs[8][RR];
    __shared__ float s_rc[8][RR];

    // dtype detect (int64 vs int32 cluster_id): warp 0, parallel ballot
    if (warp == 0) {
        const int* c32 = (const int*)cid_raw;
        int ok = 1;
        #pragma unroll
        for (int k = 0; k < 4; k++) {
            int idx = (lane * 4 + k) * 2;
            int lo = c32[idx], hi = c32[idx + 1];
            if (hi != 0 || (unsigned)lo >= 64u) ok = 0;
        }
        unsigned bal = __ballot_sync(0xffffffffu, ok);
        if (lane == 0) s_is64 = (bal == 0xffffffffu);
    }

    float s0=0.f, s1=0.f, c0=0.f, c1=0.f;

    if (active) {
        const float* base = seq + ((size_t)b * TT * NN + n0) * FF;
        #pragma unroll 12
        for (int t = 0; t < TT; t++) {
            const float* p = base + (size_t)t * ROW;
            float2 v0 = __ldg((const float2*)(p));      // floats 0,1
            float2 v1 = __ldg((const float2*)(p + 2));  // floats 2,3
            float a0 = v0.x, a1 = v1.y;                 // ch0 of n0, n0+1
            if (a0 == a0) { s0 += a0; c0 += 1.f; }
            if (a1 == a1) { s1 += a1; c1 += 1.f; }
        }
    }

    float m0 = s0/c0, m1 = s1/c1;           // 0/0 -> NaN (all-NaN node)

    if (active) {
        float2 r; r.x = m0; r.y = m1;
        float* ob = out + (size_t)b * (HH * NN) + n0;
        #pragma unroll
        for (int h = 0; h < HH; h++)
            *(float2*)(ob + h * NN) = r;

        // record all-NaN nodes (expected never: 0.05^36)
        if (c0 == 0.f) { int i = atomicAdd(&g_nan_count, 1); if (i < NAN_CAP) g_nan_list[i] = b * NN + n0;     }
        if (c1 == 0.f) { int i = atomicAdd(&g_nan_count, 1); if (i < NAN_CAP) g_nan_list[i] = b * NN + n0 + 1; }
    }

    __syncthreads();   // s_is64 ready

    int r0 = -1, r1 = -1;
    if (active) {
        if (s_is64) {
            const long long* c64 = (const long long*)cid_raw;
            r0 = (int)c64[n0]; r1 = (int)c64[n0 + 1];
        } else {
            const int* c32 = (const int*)cid_raw;
            int2 cv = __ldg((const int2*)(c32 + n0));
            r0 = cv.x; r1 = cv.y;
        }
    }
    float v0 = (c0>0.f)?m0:0.f, v1 = (c1>0.f)?m1:0.f;
    float k0 = (c0>0.f)?1.f:0.f, k1 = (c1>0.f)?1.f:0.f;

    // per-warp region reduction (deterministic shuffles)
    #pragma unroll
    for (int r = 0; r < RR; r++) {
        float s = 0.f, c = 0.f;
        if (r0 == r) { s += v0; c += k0; }
        if (r1 == r) { s += v1; c += k1; }
        #pragma unroll
        for (int o = 16; o > 0; o >>= 1) {
            s += __shfl_xor_sync(0xffffffffu, s, o);
            c += __shfl_xor_sync(0xffffffffu, c, o);
        }
        if (lane == 0) { s_rs[warp][r] = s; s_rc[warp][r] = c; }
    }
    __syncthreads();

    if (tid < RR) {
        float s = 0.f, c = 0.f;
        #pragma unroll
        for (int w = 0; w < 8; w++) { s += s_rs[w][tid]; c += s_rc[w][tid]; }
        g_ps[b][chunk][tid] = s;
        g_pc[b][chunk][tid] = c;
    }
}

// ---------------------------------------------------------------------------
// Kernel B: finalize. 1 block, 256 threads. Fixed-order reductions.
__global__ void k_fin(float* __restrict__ out) {
    __shared__ float s_rsum[BB*RR];
    __shared__ float s_rcnt[BB*RR];
    __shared__ float sh0[256], sh1[256], sh2[256], sh3[256];
    const int t = threadIdx.x;

    for (int i = t; i < BB*RR; i += 256) {
        int b = i / RR, r = i % RR;
        float s = 0.f, c = 0.f;
        #pragma unroll
        for (int ch = 0; ch < CHUNKS; ch++) { s += g_ps[b][ch][r]; c += g_pc[b][ch][r]; }
        s_rsum[i] = s; s_rcnt[i] = c;
    }
    __syncthreads();

    // g1 = total_sum/total_cnt (regions partition nodes; H-tiling cancels);
    // g2 = mean of valid region-means
    float ts=0.f, tc=0.f, ms=0.f, mc=0.f;
    for (int i = t; i < BB*RR; i += 256) {
        float s = s_rsum[i], c = s_rcnt[i];
        ts += s; tc += c;
        if (c > 0.f) { ms += s / c; mc += 1.f; }
    }
    sh0[t]=ts; sh1[t]=tc; sh2[t]=ms; sh3[t]=mc;
    __syncthreads();
    #pragma unroll
    for (int o = 128; o > 0; o >>= 1) {
        if (t < o) { sh0[t]+=sh0[t+o]; sh1[t]+=sh1[t+o]; sh2[t]+=sh2[t+o]; sh3[t]+=sh3[t+o]; }
        __syncthreads();
    }
    const float g1 = sh0[0] / sh1[0];
    const float g2 = sh2[0] / sh3[0];

    // regional output [B, H, R] (independent of h)
    for (int i = t; i < REG_ELEMS; i += 256) {
        int b = i / (HH * RR);
        int r = i % RR;
        float c = s_rcnt[b * RR + r];
        out[PRED_ELEMS + i] = (c > 0.f) ? (s_rsum[b * RR + r] / c) : g2;
    }

    // NaN fixup in pred output (expected 0 entries; order-independent writes)
    int cnt = g_nan_count;
    if (cnt > NAN_CAP) cnt = NAN_CAP;
    for (int i = t; i < cnt; i += 256) {
        int code = g_nan_list[i];
        int b = code / NN, n = code % NN;
        float* ob = out + (size_t)b * (HH * NN) + n;
        #pragma unroll
        for (int h = 0; h < HH; h++) ob[h * NN] = g1;
    }
    __syncthreads();
    if (t == 0) g_nan_count = 0;   // reset for next graph replay
}

// ---------------------------------------------------------------------------
extern "C" void kernel_launch(void* const* d_in, const int* in_sizes, int n_in,
                              void* d_out, int out_size) {
    const float* seq = (const float*)d_in[0];
    const void*  cid = d_in[1];
    float* out = (float*)d_out;

    dim3 grid(CHUNKS, BB);
    k_main<<<grid, 256>>>(seq, cid, out);
    k_fin<<<1, 256>>>(out);
}

// round 16
// speedup vs baseline: 1.5272x; 1.2310x over previous
#include <cuda_runtime.h>
#include <cuda_bf16.h>

#define BB 32
#define TT 36
#define NN 10000
#define FF 3
#define RR 20
#define HH 10
#define CHUNKS 10                           // blocks per batch; 1000 nodes each
#define NODES_PER_CHUNK (NN / CHUNKS)       // 1000
#define ACTIVE_THREADS (NODES_PER_CHUNK/4)  // 250 threads own 4 nodes each
#define PRED_ELEMS (BB*HH*NN)               // 3,200,000
#define REG_ELEMS  (BB*HH*RR)               // 6,400
#define NAN_CAP    (BB*NN)

// Scratch (device globals — no allocation allowed)
__device__ float g_ps[BB][CHUNKS][RR];      // partial region sums
__device__ float g_pc[BB][CHUNKS][RR];      // partial region counts
__device__ int   g_nan_count = 0;
__device__ int   g_nan_list[NAN_CAP];

// ---------------------------------------------------------------------------
// Kernel A (identical to the proven 39.4us version): stream + time-mean +
// pred write + region partials. grid = (CHUNKS, BB), block = 256.
__global__ void __launch_bounds__(256) k_main(const float* __restrict__ seq,
                                              const void* __restrict__ cid_raw,
                                              float* __restrict__ out) {
    const int tid   = threadIdx.x;
    const int lane  = tid & 31;
    const int warp  = tid >> 5;
    const int chunk = blockIdx.x;
    const int b     = blockIdx.y;

    __shared__ int   s_is64;
    __shared__ float s_rs[8][RR];
    __shared__ float s_rc[8][RR];

    // dtype detect (int64 vs int32 cluster_id): warp 0, parallel ballot
    if (warp == 0) {
        const int* c32 = (const int*)cid_raw;
        int ok = 1;
        #pragma unroll
        for (int k = 0; k < 4; k++) {
            int idx = (lane * 4 + k) * 2;
            int lo = c32[idx], hi = c32[idx + 1];
            if (hi != 0 || (unsigned)lo >= 64u) ok = 0;
        }
        unsigned bal = __ballot_sync(0xffffffffu, ok);
        if (lane == 0) s_is64 = (bal == 0xffffffffu);
    }

    const bool active = (tid < ACTIVE_THREADS);
    const int n0 = chunk * NODES_PER_CHUNK + tid * 4;

    float s0=0.f,s1=0.f,s2=0.f,s3=0.f;
    float c0=0.f,c1=0.f,c2=0.f,c3=0.f;

    if (active) {
        const float* base = seq + ((size_t)b * TT * NN + n0) * FF;
        #pragma unroll 6
        for (int t = 0; t < TT; t++) {
            const float* p = base + (size_t)t * (NN * FF);
            float4 v0 = __ldg((const float4*)(p));
            float4 v1 = __ldg((const float4*)(p + 4));
            float4 v2 = __ldg((const float4*)(p + 8));
            float a0 = v0.x, a1 = v0.w, a2 = v1.z, a3 = v2.y;
            if (a0 == a0) { s0 += a0; c0 += 1.f; }
            if (a1 == a1) { s1 += a1; c1 += 1.f; }
            if (a2 == a2) { s2 += a2; c2 += 1.f; }
            if (a3 == a3) { s3 += a3; c3 += 1.f; }
        }
    }

    float m0 = s0/c0, m1 = s1/c1, m2 = s2/c2, m3 = s3/c3;  // 0/0 -> NaN

    if (active) {
        float4 r; r.x = m0; r.y = m1; r.z = m2; r.w = m3;
        float* ob = out + (size_t)b * (HH * NN) + n0;
        #pragma unroll
        for (int h = 0; h < HH; h++)
            *(float4*)(ob + h * NN) = r;

        // record all-NaN nodes (expected never: 0.05^36)
        if (c0 == 0.f) { int i = atomicAdd(&g_nan_count, 1); if (i < NAN_CAP) g_nan_list[i] = b * NN + n0;     }
        if (c1 == 0.f) { int i = atomicAdd(&g_nan_count, 1); if (i < NAN_CAP) g_nan_list[i] = b * NN + n0 + 1; }
        if (c2 == 0.f) { int i = atomicAdd(&g_nan_count, 1); if (i < NAN_CAP) g_nan_list[i] = b * NN + n0 + 2; }
        if (c3 == 0.f) { int i = atomicAdd(&g_nan_count, 1); if (i < NAN_CAP) g_nan_list[i] = b * NN + n0 + 3; }
    }

    __syncthreads();   // s_is64 ready

    int r0=-1, r1=-1, r2=-1, r3=-1;
    if (active) {
        if (s_is64) {
            const long long* c64 = (const long long*)cid_raw;
            r0=(int)c64[n0]; r1=(int)c64[n0+1]; r2=(int)c64[n0+2]; r3=(int)c64[n0+3];
        } else {
            const int* c32 = (const int*)cid_raw;
            int4 cv = __ldg((const int4*)(c32 + n0));
            r0=cv.x; r1=cv.y; r2=cv.z; r3=cv.w;
        }
    }
    float v0 = (c0>0.f)?m0:0.f, v1 = (c1>0.f)?m1:0.f;
    float v2 = (c2>0.f)?m2:0.f, v3 = (c3>0.f)?m3:0.f;
    float k0 = (c0>0.f)?1.f:0.f, k1 = (c1>0.f)?1.f:0.f;
    float k2 = (c2>0.f)?1.f:0.f, k3 = (c3>0.f)?1.f:0.f;

    // per-warp region reduction (deterministic shuffles)
    #pragma unroll
    for (int r = 0; r < RR; r++) {
        float s = 0.f, c = 0.f;
        if (r0 == r) { s += v0; c += k0; }
        if (r1 == r) { s += v1; c += k1; }
        if (r2 == r) { s += v2; c += k2; }
        if (r3 == r) { s += v3; c += k3; }
        #pragma unroll
        for (int o = 16; o > 0; o >>= 1) {
            s += __shfl_xor_sync(0xffffffffu, s, o);
            c += __shfl_xor_sync(0xffffffffu, c, o);
        }
        if (lane == 0) { s_rs[warp][r] = s; s_rc[warp][r] = c; }
    }
    __syncthreads();

    if (tid < RR) {
        float s = 0.f, c = 0.f;
        #pragma unroll
        for (int w = 0; w < 8; w++) { s += s_rs[w][tid]; c += s_rc[w][tid]; }
        g_ps[b][chunk][tid] = s;
        g_pc[b][chunk][tid] = c;
    }

#if __CUDA_ARCH__ >= 900
    // allow the PDL-gated finalize kernel to proceed once all blocks pass here
    cudaTriggerProgrammaticLaunchCompletion();
#endif
}

// ---------------------------------------------------------------------------
// Kernel B: finalize. 1 block, 640 threads (one per (b,r) pair).
// Launched with ProgrammaticStreamSerialization; body gated on
// cudaGridDependencySynchronize so its launch overlaps k_main's drain.
__global__ void __launch_bounds__(640) k_fin(float* __restrict__ out) {
    __shared__ float s_rsum[BB*RR];
    __shared__ float s_rcnt[BB*RR];
    __shared__ float sh0[640], sh1[640], sh2[640], sh3[640];
    const int t = threadIdx.x;

#if __CUDA_ARCH__ >= 900
    cudaGridDependencySynchronize();   // wait for k_main's writes to be visible
#endif

    // one thread per (b,r): reduce its 10 chunk partials (fixed order)
    const int b = t / RR, r = t % RR;
    float s = 0.f, c = 0.f;
    #pragma unroll
    for (int ch = 0; ch < CHUNKS; ch++) { s += g_ps[b][ch][r]; c += g_pc[b][ch][r]; }
    s_rsum[t] = s; s_rcnt[t] = c;

    // global reductions: g1 = total_sum/total_cnt (regions partition nodes;
    // H-tiling cancels); g2 = mean of valid region-means
    sh0[t] = s;
    sh1[t] = c;
    sh2[t] = (c > 0.f) ? (s / c) : 0.f;
    sh3[t] = (c > 0.f) ? 1.f : 0.f;
    __syncthreads();
    // fold 640 -> 512, then power-of-2 tree (fixed order -> deterministic)
    if (t < 128) { sh0[t]+=sh0[t+512]; sh1[t]+=sh1[t+512]; sh2[t]+=sh2[t+512]; sh3[t]+=sh3[t+512]; }
    __syncthreads();
    #pragma unroll
    for (int o = 256; o > 0; o >>= 1) {
        if (t < o) { sh0[t]+=sh0[t+o]; sh1[t]+=sh1[t+o]; sh2[t]+=sh2[t+o]; sh3[t]+=sh3[t+o]; }
        __syncthreads();
    }
    const float g1 = sh0[0] / sh1[0];
    const float g2 = sh2[0] / sh3[0];

    // regional output [B, H, R]: thread (b,r) writes its 10 h-copies
    {
        float c2 = s_rcnt[t];
        float v  = (c2 > 0.f) ? (s_rsum[t] / c2) : g2;
        float* ob = out + PRED_ELEMS + b * (HH * RR) + r;
        #pragma unroll
        for (int h = 0; h < HH; h++) ob[h * RR] = v;
    }

    // NaN fixup in pred output (expected 0 entries; order-independent writes)
    int cnt = g_nan_count;
    if (cnt > NAN_CAP) cnt = NAN_CAP;
    for (int i = t; i < cnt; i += 640) {
        int code = g_nan_list[i];
        int bb = code / NN, n = code % NN;
        float* ob = out + (size_t)bb * (HH * NN) + n;
        #pragma unroll
        for (int h = 0; h < HH; h++) ob[h * NN] = g1;
    }
    __syncthreads();
    if (t == 0) g_nan_count = 0;   // reset for next graph replay
}

// ---------------------------------------------------------------------------
extern "C" void kernel_launch(void* const* d_in, const int* in_sizes, int n_in,
                              void* d_out, int out_size) {
    const float* seq = (const float*)d_in[0];
    const void*  cid = d_in[1];
    float* out = (float*)d_out;

    dim3 grid(CHUNKS, BB);
    k_main<<<grid, 256>>>(seq, cid, out);

    // PDL launch of the finalize: overlaps its launch latency with k_main.
    cudaLaunchConfig_t cfg = {};
    cfg.gridDim  = dim3(1, 1, 1);
    cfg.blockDim = dim3(640, 1, 1);
    cfg.dynamicSmemBytes = 0;
    cfg.stream = 0;                       // same (legacy) stream as k_main
    cudaLaunchAttribute attr[1];
    attr[0].id = cudaLaunchAttributeProgrammaticStreamSerialization;
    attr[0].val.programmaticStreamSerializationAllowed = 1;
    cfg.attrs = attr;
    cfg.numAttrs = 1;
    cudaError_t e = cudaLaunchKernelEx(&cfg, k_fin, out);
    if (e != cudaSuccess) {
        // fallback: plain launch (keeps correctness if PDL unsupported)
        k_fin<<<1, 640>>>(out);
    }
}